// round 3
// baseline (speedup 1.0000x reference)
#include <cuda_runtime.h>
#include <cstdint>

// compressor_17454747091102: 8-voter bitwise majority.
// out packed word j, bit i = 1 iff >=5 of 8 voters have bit i of word j set.
// Output dtype float32: store (float)(int32)packed_word.

__device__ __forceinline__ void fa(uint32_t a, uint32_t b, uint32_t c,
                                   uint32_t& s, uint32_t& cy) {
    s  = a ^ b ^ c;
    cy = (a & b) | (c & (a ^ b));   // one LOP3 each
}

__device__ __forceinline__ uint32_t maj8(const uint32_t w[8]) {
    uint32_t sa, ca, sb, cb;
    fa(w[0], w[1], w[2], sa, ca);
    fa(w[3], w[4], w[5], sb, cb);
    uint32_t sc = w[6] ^ w[7];
    uint32_t cc = w[6] & w[7];

    uint32_t S0, cd;
    fa(sa, sb, sc, S0, cd);
    uint32_t s1p, ce;
    fa(ca, cb, cc, s1p, ce);

    uint32_t S1 = s1p ^ cd;
    uint32_t cf = s1p & cd;
    uint32_t S2 = ce ^ cf;
    uint32_t S3 = ce & cf;
    // popcount = S0 + 2*S1 + 4*S2 + 8*S3 ; set iff >= 5
    return S3 | (S2 & (S1 | S0));
}

__device__ __forceinline__ int4 ldcs_int4(const int4* p) {
    int4 v;
    asm volatile("ld.global.cs.v4.u32 {%0,%1,%2,%3}, [%4];"
                 : "=r"(v.x), "=r"(v.y), "=r"(v.z), "=r"(v.w) : "l"(p));
    return v;
}

__device__ __forceinline__ void stcs_float4(float4* p, float4 v) {
    asm volatile("st.global.cs.v4.f32 [%0], {%1,%2,%3,%4};"
                 :: "l"(p), "f"(v.x), "f"(v.y), "f"(v.z), "f"(v.w) : "memory");
}

// 2 int4 chunks per thread; all 16 loads front-batched for MLP=16.
__global__ void __launch_bounds__(256, 1)
majority_vote_kernel(const int4* __restrict__ src, float4* __restrict__ out, int m4) {
    int t = blockIdx.x * blockDim.x + threadIdx.x;
    int base = t * 2;                 // adjacent pair: warp covers 1KB/voter
    if (base + 1 >= m4 + 1) { }       // exact grid; no real guard needed
    if (base >= m4) return;

    int4 va[8], vb[8];
    #pragma unroll
    for (int v = 0; v < 8; v++) va[v] = ldcs_int4(src + (size_t)v * m4 + base);
    #pragma unroll
    for (int v = 0; v < 8; v++) vb[v] = ldcs_int4(src + (size_t)v * m4 + base + 1);

    uint32_t wx[8], wy[8], wz[8], ww[8];
    #pragma unroll
    for (int v = 0; v < 8; v++) {
        wx[v] = (uint32_t)va[v].x; wy[v] = (uint32_t)va[v].y;
        wz[v] = (uint32_t)va[v].z; ww[v] = (uint32_t)va[v].w;
    }
    float4 ra;
    ra.x = __int2float_rn((int)maj8(wx));
    ra.y = __int2float_rn((int)maj8(wy));
    ra.z = __int2float_rn((int)maj8(wz));
    ra.w = __int2float_rn((int)maj8(ww));
    stcs_float4(out + base, ra);

    #pragma unroll
    for (int v = 0; v < 8; v++) {
        wx[v] = (uint32_t)vb[v].x; wy[v] = (uint32_t)vb[v].y;
        wz[v] = (uint32_t)vb[v].z; ww[v] = (uint32_t)vb[v].w;
    }
    float4 rb;
    rb.x = __int2float_rn((int)maj8(wx));
    rb.y = __int2float_rn((int)maj8(wy));
    rb.z = __int2float_rn((int)maj8(wz));
    rb.w = __int2float_rn((int)maj8(ww));
    stcs_float4(out + base + 1, rb);
}

extern "C" void kernel_launch(void* const* d_in, const int* in_sizes, int n_in,
                              void* d_out, int out_size) {
    const int* src = (const int*)d_in[1];
    long long n_src = in_sizes[1];
    if (n_in > 1 && in_sizes[0] > in_sizes[1]) { src = (const int*)d_in[0]; n_src = in_sizes[0]; }

    int M  = (int)(n_src / 8);      // packed words per voter == out_size
    int m4 = M / 4;                 // int4 chunks (262144)
    int chunks_per_thread = 2;
    int threads = 256;
    int total_threads = (m4 + chunks_per_thread - 1) / chunks_per_thread;
    int blocks = (total_threads + threads - 1) / threads;   // 512
    majority_vote_kernel<<<blocks, threads>>>((const int4*)src, (float4*)d_out, m4);
}